// round 13
// baseline (speedup 1.0000x reference)
#include <cuda_runtime.h>

// Problem constants (fixed shapes from the reference)
constexpr int Bn = 4;       // batch
constexpr int Nn = 16384;   // points per cloud
constexpr int Pn = 1024;    // npoint (FPS samples)
constexpr int Sn = 64;      // nsample (ball query)

// Scratch: ball query indices (B,P,S). 1 MB.
__device__ int g_ball_idx[Bn * Pn * Sn];

// ---- packed f32x2 helpers (sm_100+). Per-lane semantics identical to
// __fadd_rn / __fmul_rn / __fmaf_rn.
typedef unsigned long long ull;
__device__ __forceinline__ ull pk2(float lo, float hi) {
    ull r; asm("mov.b64 %0,{%1,%2};" : "=l"(r) : "f"(lo), "f"(hi)); return r;
}
__device__ __forceinline__ void upk2(ull v, float& lo, float& hi) {
    asm("mov.b64 {%0,%1},%2;" : "=f"(lo), "=f"(hi) : "l"(v));
}
__device__ __forceinline__ ull addx2(ull a, ull b) {
    ull r; asm("add.rn.f32x2 %0,%1,%2;" : "=l"(r) : "l"(a), "l"(b)); return r;
}
__device__ __forceinline__ ull mulx2(ull a, ull b) {
    ull r; asm("mul.rn.f32x2 %0,%1,%2;" : "=l"(r) : "l"(a), "l"(b)); return r;
}
__device__ __forceinline__ ull fmax2(ull a, ull b, ull c) {   // a*b+c
    ull r; asm("fma.rn.f32x2 %0,%1,%2,%3;" : "=l"(r) : "l"(a), "l"(b), "l"(c));
    return r;
}
__device__ __forceinline__ unsigned mapa_sh(unsigned addr, int rank) {
    unsigned r;
    asm("mapa.shared::cluster.u32 %0, %1, %2;" : "=r"(r) : "r"(addr), "r"(rank));
    return r;
}
__device__ __forceinline__ ull umax64(ull a, ull b) { return a > b ? a : b; }

// ---------------------------------------------------------------------------
// Kernel 1: Furthest Point Sampling — 8-CTA cluster per batch.
// Each CTA (256 threads) owns 2048 points fully in registers (packed f32x2);
// full-cloud coord copy in smem for the per-iter broadcast read.
// Per iteration (NO __syncthreads, NO atomics, NO barrier.cluster):
//   redux.max (dist bits) + gated redux.min (global idx) per warp,
//   lane0 -> skey8[wid], key TAG-STAMPED with the iteration (bits 14..23),
//   warp0 lanes 0..7 poll skey8 until all 8 warp tags are current, reduce,
//   and store the block key to destination CTA = lane (8 parallel remote
//   stores). Meanwhile warps 1..7 head straight to the mailbox poll.
//   Every thread polls its LOCAL mailbox (4x LDS.128) until all 8 CTA slots
//   carry the tag, then max key => (max dist, then min global idx).
// Safety: no warp can pass the mailbox poll of iteration `it` (and thus
// overwrite its skey slot for it+1) before warp0 consumed all tag-it keys,
// because the mailbox only fills after warp0's send.
// ---------------------------------------------------------------------------
constexpr int FPS_CL   = 8;                 // CTAs per batch (cluster size)
constexpr int FPS_PART = Nn / FPS_CL;       // 2048 points per CTA
constexpr int FPS_NT   = 256;               // threads per CTA
constexpr int FPS_PPT  = FPS_PART / FPS_NT; // 8 points per thread
constexpr int FPS_NPAIR = FPS_PPT / 2;      // 4 packed pairs per thread
// smem: float sxy[2*Nn] + szf[Nn], then ull skey8[8] + mbox[2][8]
constexpr int FPS_SMEM = 3 * Nn * 4 + 24 * 8;

__global__ __launch_bounds__(FPS_NT, 1) __cluster_dims__(FPS_CL, 1, 1)
void fps_kernel(const float* __restrict__ xyz, float* __restrict__ new_xyz)
{
    const int b = blockIdx.x / FPS_CL;
    const int r = blockIdx.x % FPS_CL;     // cluster rank
    const float* pts = xyz + (size_t)b * Nn * 3;

    extern __shared__ float sm[];
    float2* sxy   = reinterpret_cast<float2*>(sm);   // [Nn]
    float*  szf   = sm + 2 * Nn;                     // [Nn]
    ull*    skey8 = reinterpret_cast<ull*>(sm + 3 * Nn);  // [8]
    ull*    mbox  = skey8 + 8;                       // [2][8]

    const int tid  = threadIdx.x;
    const int lane = tid & 31;
    const int wid  = tid >> 5;

    // Stage the full cloud into this CTA's smem (for broadcasts).
    for (int p = tid; p < Nn; p += FPS_NT) {
        float x = pts[p * 3 + 0];
        float y = pts[p * 3 + 1];
        float z = pts[p * 3 + 2];
        sxy[p] = make_float2(x, y);
        szf[p] = z;
    }
    if (tid < 16) mbox[tid] = 0ull;        // tag 0 (never used: it >= 1)
    if (tid < 8)  skey8[tid] = 0ull;       // tag 0
    __syncthreads();
    // Mailbox init must be cluster-visible before any remote store (startup
    // only — no cluster barrier inside the loop).
    asm volatile("barrier.cluster.arrive.aligned;" ::: "memory");
    asm volatile("barrier.cluster.wait.aligned;"   ::: "memory");

    // Remote mailbox address: thread t<8 owns destination CTA t, slot r.
    const unsigned mbox_l  = (unsigned)__cvta_generic_to_shared(mbox);
    const unsigned skey_l  = (unsigned)__cvta_generic_to_shared(skey8);
    const unsigned rm_dest = (tid < FPS_CL)
        ? mapa_sh(mbox_l + (unsigned)(r * 8), tid) : 0u;

    // This CTA's 2048-point partition -> registers, packed pairs.
    const int base = r * FPS_PART;
    ull rx[FPS_NPAIR], ry[FPS_NPAIR], rz[FPS_NPAIR];
#pragma unroll
    for (int j = 0; j < FPS_NPAIR; ++j) {
        const int pA = base + j * FPS_NT + tid;
        const int pB = pA + FPS_NPAIR * FPS_NT;
        float2 a = sxy[pA], c = sxy[pB];
        rx[j] = pk2(a.x, c.x);
        ry[j] = pk2(a.y, c.y);
        rz[j] = pk2(szf[pA], szf[pB]);
    }
    float md[FPS_PPT];
#pragma unroll
    for (int k = 0; k < FPS_PPT; ++k) md[k] = 1e10f;   // matches jnp 1e10 init

    // First selected point is index 0.
    float qx = sxy[0].x, qy = sxy[0].y, qz = szf[0];
    if (r == 0 && tid == 0) {
        float* o = new_xyz + (size_t)b * Pn * 3;
        o[0] = qx; o[1] = qy; o[2] = qz;
    }

    for (int it = 1; it < Pn; ++it) {
        const ull nqx = pk2(-qx, -qx);
        const ull nqy = pk2(-qy, -qy);
        const ull nqz = pk2(-qz, -qz);

        float vm0 = -1.0f, vm1 = -1.0f;
#pragma unroll
        for (int j = 0; j < FPS_NPAIR; ++j) {
            ull dx = addx2(rx[j], nqx);            // == __fadd_rn(x, -qx)
            ull dy = addx2(ry[j], nqy);
            ull dz = addx2(rz[j], nqz);
            ull s  = addx2(addx2(mulx2(dx, dx), mulx2(dy, dy)), mulx2(dz, dz));
            float d0, d1; upk2(s, d0, d1);
            md[j]             = fminf(md[j],             d0);
            md[j + FPS_NPAIR] = fminf(md[j + FPS_NPAIR], d1);
            vm0 = fmaxf(vm0, md[j]);
            vm1 = fmaxf(vm1, md[j + FPS_NPAIR]);
        }
        const unsigned vb = __float_as_uint(fmaxf(vm0, vm1));

        // Warp max of distance bits (nonneg floats: bit order == float order),
        // then min global index among the warp's winners (first-match tiebreak).
        const unsigned wb = __reduce_max_sync(0xffffffffu, vb);
        unsigned loc = 0xffffffffu;
        if (vb == wb) {
            int bk = 0;
#pragma unroll
            for (int m = FPS_PPT - 1; m >= 0; --m)
                if (__float_as_uint(md[m]) == wb) bk = m;   // smallest slot
            loc = (unsigned)(base + bk * FPS_NT + tid);
        }
        const unsigned lmin = __reduce_min_sync(0xffffffffu, loc);  // <= 16383

        const int buf = it & 1;
        const unsigned tag = (unsigned)(it & 0x3FF);

        // Tag-stamped warp key (tag bits equal across warps -> ordering
        // unaffected by the stamp).
        if (lane == 0)
            skey8[wid] = ((ull)wb << 32) | ((ull)tag << 14)
                       | (unsigned)(0x3FFF - lmin);

        if (tid < FPS_CL) {
            // Sender lanes: poll skey8 until all 8 warp tags are current,
            // reduce, store to destination CTA = lane (8 parallel stores).
            ull s0, s1, s2, s3, s4, s5, s6, s7;
            for (;;) {
                asm volatile("ld.volatile.shared.v2.u64 {%0,%1},[%2];"
                             : "=l"(s0), "=l"(s1) : "r"(skey_l));
                asm volatile("ld.volatile.shared.v2.u64 {%0,%1},[%2];"
                             : "=l"(s2), "=l"(s3) : "r"(skey_l + 16));
                asm volatile("ld.volatile.shared.v2.u64 {%0,%1},[%2];"
                             : "=l"(s4), "=l"(s5) : "r"(skey_l + 32));
                asm volatile("ld.volatile.shared.v2.u64 {%0,%1},[%2];"
                             : "=l"(s6), "=l"(s7) : "r"(skey_l + 48));
                unsigned bad =
                    (((unsigned)(s0 >> 14) & 0x3FFu) ^ tag) |
                    (((unsigned)(s1 >> 14) & 0x3FFu) ^ tag) |
                    (((unsigned)(s2 >> 14) & 0x3FFu) ^ tag) |
                    (((unsigned)(s3 >> 14) & 0x3FFu) ^ tag) |
                    (((unsigned)(s4 >> 14) & 0x3FFu) ^ tag) |
                    (((unsigned)(s5 >> 14) & 0x3FFu) ^ tag) |
                    (((unsigned)(s6 >> 14) & 0x3FFu) ^ tag) |
                    (((unsigned)(s7 >> 14) & 0x3FFu) ^ tag);
                if (!bad) break;
            }
            ull bk = umax64(umax64(umax64(s0, s1), umax64(s2, s3)),
                            umax64(umax64(s4, s5), umax64(s6, s7)));
            asm volatile("st.shared::cluster.u64 [%0], %1;"
                         :: "r"(rm_dest + (unsigned)(buf * FPS_CL * 8)),
                            "l"(bk) : "memory");
        }

        // Poll local mailbox (4x LDS.128) until all 8 slots carry this tag.
        const unsigned mba = mbox_l + (unsigned)(buf * FPS_CL * 8);
        ull k[8];
        for (;;) {
            asm volatile("ld.volatile.shared.v2.u64 {%0,%1},[%2];"
                         : "=l"(k[0]), "=l"(k[1]) : "r"(mba));
            asm volatile("ld.volatile.shared.v2.u64 {%0,%1},[%2];"
                         : "=l"(k[2]), "=l"(k[3]) : "r"(mba + 16));
            asm volatile("ld.volatile.shared.v2.u64 {%0,%1},[%2];"
                         : "=l"(k[4]), "=l"(k[5]) : "r"(mba + 32));
            asm volatile("ld.volatile.shared.v2.u64 {%0,%1},[%2];"
                         : "=l"(k[6]), "=l"(k[7]) : "r"(mba + 48));
            unsigned bad = 0;
#pragma unroll
            for (int q = 0; q < 8; ++q)
                bad |= ((unsigned)(k[q] >> 14) & 0x3FFu) ^ tag;
            if (!bad) break;
        }

        // Winner across CTAs: max packed key (max dist, then min index).
        ull kk = umax64(umax64(umax64(k[0], k[1]), umax64(k[2], k[3])),
                        umax64(umax64(k[4], k[5]), umax64(k[6], k[7])));
        const int sel = (int)(0x3FFFu - ((unsigned)kk & 0x3FFFu));

        float2 qv = sxy[sel];                      // local smem broadcast
        qx = qv.x; qy = qv.y; qz = szf[sel];
        if (r == 0 && tid == 0) {
            float* o = new_xyz + ((size_t)b * Pn + it) * 3;
            o[0] = qx; o[1] = qy; o[2] = qz;
        }
    }

    // No CTA may exit while peers might still write into its mailbox.
    asm volatile("barrier.cluster.arrive.aligned;" ::: "memory");
    asm volatile("barrier.cluster.wait.aligned;"   ::: "memory");
}

// ---------------------------------------------------------------------------
// Kernel 2: Ball query — one warp per center, 8 centers (same batch) per block.
// 128-point chunks: 12 batched loads (MLP=12 hides L2 latency), then 4
// ballots processed in index order; exit check per chunk. Output identical
// to the scalar loop (same order, same pos<Sn guards, same `first` logic).
// ---------------------------------------------------------------------------
__global__ __launch_bounds__(256)
void ballq_kernel(const float* __restrict__ xyz, const float* __restrict__ new_xyz)
{
    const int wglobal = blockIdx.x * 8 + (threadIdx.x >> 5);  // center id 0..4095
    const int b    = wglobal >> 10;
    const int lane = threadIdx.x & 31;

    const float* pts = xyz + (size_t)b * Nn * 3;
    const float* c   = new_xyz + (size_t)wglobal * 3;
    const float cx = c[0], cy = c[1], cz = c[2];
    int* oidx = g_ball_idx + (size_t)wglobal * Sn;

    const float R2 = (float)(0.3 * 0.3);   // same double->f32 path as JAX

    int  cnt   = 0;
    int  first = 0;
    bool have  = false;

    for (int base = 0; base < Nn; base += 128) {
        float xs[4], ys[4], zs[4];
#pragma unroll
        for (int t = 0; t < 4; ++t) {
            const int j = base + t * 32 + lane;
            xs[t] = pts[j * 3 + 0];
            ys[t] = pts[j * 3 + 1];
            zs[t] = pts[j * 3 + 2];
        }
#pragma unroll
        for (int t = 0; t < 4; ++t) {
            const int j = base + t * 32 + lane;
            float dx = __fadd_rn(cx, -xs[t]);
            float dy = __fadd_rn(cy, -ys[t]);
            float dz = __fadd_rn(cz, -zs[t]);
            float d  = __fadd_rn(__fadd_rn(__fmul_rn(dx, dx), __fmul_rn(dy, dy)),
                                 __fmul_rn(dz, dz));
            bool in = d < R2;
            unsigned m = __ballot_sync(0xffffffffu, in);
            if (m) {
                if (!have) { first = base + t * 32 + (__ffs(m) - 1); have = true; }
                if (in) {
                    int pos = cnt + __popc(m & ((1u << lane) - 1u));
                    if (pos < Sn) oidx[pos] = j;
                }
                cnt += __popc(m);
            }
        }
        if (cnt >= Sn) break;
    }
    if (cnt < Sn) {
        for (int s = cnt + lane; s < Sn; s += 32) oidx[s] = first;  // 0 if none
    }
}

// ---------------------------------------------------------------------------
// Kernel 3: gather + MLP(6->64->64->128, relu) + max over samples. (unchanged)
// ---------------------------------------------------------------------------
constexpr int SW_FLOATS = 384 + 64 + 4096 + 64 + 64 * 132 + 128;  // 13184

__global__ __launch_bounds__(128)
void group_mlp_kernel(const float* __restrict__ xyz, const float* __restrict__ features,
                      const float* __restrict__ W1, const float* __restrict__ b1,
                      const float* __restrict__ W2, const float* __restrict__ b2,
                      const float* __restrict__ W3, const float* __restrict__ b3,
                      const float* __restrict__ new_xyz, float* __restrict__ out_feat)
{
    extern __shared__ float sw[];
    float* w1t = sw;                 // [6][64]   w1t[c*64+o] = W1[o][c]
    float* b1s = w1t + 384;          // [64]
    float* w2s = b1s + 64;           // [64][64]  row i = W2[i][:]
    float* b2s = w2s + 4096;         // [64]
    float* w3t = b2s + 64;           // [64][132] w3t[i*132+o] = W3[o][i]
    float* b3s = w3t + 64 * 132;     // [128]

    const int tid = threadIdx.x;

    for (int j = tid; j < 384; j += 128) {
        int cc = j >> 6, o = j & 63;
        w1t[j] = W1[o * 6 + cc];
    }
    if (tid < 64)  b1s[tid] = b1[tid];
    for (int j = tid; j < 4096; j += 128) w2s[j] = W2[j];
    if (tid < 64)  b2s[tid] = b2[tid];
    for (int j = tid; j < 8192; j += 128) {          // coalesced read, ~4-way STS
        int i = j & 63, o = j >> 6;
        w3t[i * 132 + o] = W3[j];
    }
    if (tid < 128) b3s[tid] = b3[tid];
    __syncthreads();

    const int cl = tid >> 6;                  // which of the 2 centers
    const int s  = tid & 63;                  // sample id
    const int center = blockIdx.x * 2 + cl;
    const int b  = center >> 10;
    const int gi = g_ball_idx[center * Sn + s];

    const float* pb = xyz      + (size_t)b * Nn * 3;
    const float* fb = features + (size_t)b * Nn * 3;
    const float* c  = new_xyz  + (size_t)center * 3;

    float g[6];
    g[0] = pb[gi * 3 + 0] - c[0];
    g[1] = pb[gi * 3 + 1] - c[1];
    g[2] = pb[gi * 3 + 2] - c[2];
    g[3] = fb[gi * 3 + 0];
    g[4] = fb[gi * 3 + 1];
    g[5] = fb[gi * 3 + 2];

    // ---- layer 1 (packed: 64 outputs in 32 ull regs) ----
    ull h1p[32];
    {
        const ull* b1u = reinterpret_cast<const ull*>(b1s);
#pragma unroll
        for (int k = 0; k < 32; ++k) h1p[k] = b1u[k];
    }
#pragma unroll
    for (int cc = 0; cc < 6; ++cc) {
        const ull gv = pk2(g[cc], g[cc]);
        const ull* wr = reinterpret_cast<const ull*>(w1t + cc * 64);
#pragma unroll
        for (int k = 0; k < 32; ++k) h1p[k] = fmax2(wr[k], gv, h1p[k]);
    }
#pragma unroll
    for (int k = 0; k < 32; ++k) {        // relu
        float lo, hi; upk2(h1p[k], lo, hi);
        h1p[k] = pk2(fmaxf(lo, 0.0f), fmaxf(hi, 0.0f));
    }

    // ---- layer 2: materialize h2[64] (h1p dies after this loop) ----
    float h2[64];
#pragma unroll
    for (int i = 0; i < 64; ++i) {
        const ulonglong2* w2r =
            reinterpret_cast<const ulonglong2*>(w2s + (i << 6));
        ull a0 = 0ull, a1 = 0ull, a2 = 0ull, a3 = 0ull;   // (0,0) packed
#pragma unroll
        for (int q = 0; q < 16; q += 2) {
            ulonglong2 w = w2r[q];
            ulonglong2 v = w2r[q + 1];
            a0 = fmax2(w.x, h1p[2 * q + 0], a0);
            a1 = fmax2(w.y, h1p[2 * q + 1], a1);
            a2 = fmax2(v.x, h1p[2 * q + 2], a2);
            a3 = fmax2(v.y, h1p[2 * q + 3], a3);
        }
        ull sp = addx2(addx2(a0, a1), addx2(a2, a3));
        float lo, hi; upk2(sp, lo, hi);
        h2[i] = fmaxf((lo + hi) + b2s[i], 0.0f);
    }

    // ---- layer 3 in two chunks of 64 outputs + warp-level max (REDUX) ----
    __shared__ unsigned red[4][128];
    const int wid = tid >> 5, lane = tid & 31;

    for (int ch = 0; ch < 2; ++ch) {
        ull accp[32];
        {
            const ull* b3u = reinterpret_cast<const ull*>(b3s + ch * 64);
#pragma unroll
            for (int k = 0; k < 32; ++k) accp[k] = b3u[k];
        }
#pragma unroll
        for (int i = 0; i < 64; ++i) {
            const ull h2p = pk2(h2[i], h2[i]);
            const ulonglong2* w3r =
                reinterpret_cast<const ulonglong2*>(w3t + i * 132 + ch * 64);
#pragma unroll
            for (int q = 0; q < 16; ++q) {
                ulonglong2 w = w3r[q];
                accp[2 * q + 0] = fmax2(w.x, h2p, accp[2 * q + 0]);
                accp[2 * q + 1] = fmax2(w.y, h2p, accp[2 * q + 1]);
            }
        }
        // relu + per-warp max over 32 samples (one REDUX per output)
#pragma unroll
        for (int k = 0; k < 32; ++k) {
            float lo, hi; upk2(accp[k], lo, hi);
            unsigned mlo = __reduce_max_sync(
                0xffffffffu, __float_as_uint(fmaxf(lo, 0.0f)));
            unsigned mhi = __reduce_max_sync(
                0xffffffffu, __float_as_uint(fmaxf(hi, 0.0f)));
            if (lane == 0) {
                red[wid][ch * 64 + 2 * k + 0] = mlo;
                red[wid][ch * 64 + 2 * k + 1] = mhi;
            }
        }
    }
    __syncthreads();

    // Combine the two warps of each center; write (B,128,P) layout.
    for (int t = tid; t < 256; t += 128) {
        int cc = t >> 7, oo = t & 127;
        unsigned v = red[2 * cc][oo] > red[2 * cc + 1][oo]
                   ? red[2 * cc][oo] : red[2 * cc + 1][oo];
        int ctr = blockIdx.x * 2 + cc;
        int bb = ctr >> 10, pp = ctr & 1023;
        out_feat[(size_t)bb * (128 * Pn) + (size_t)oo * Pn + pp] =
            __uint_as_float(v);
    }
}

// ---------------------------------------------------------------------------
// Launch: fps (clustered) -> ball query -> group+MLP.
// Output = [new_xyz | new_features].
// ---------------------------------------------------------------------------
extern "C" void kernel_launch(void* const* d_in, const int* in_sizes, int n_in,
                              void* d_out, int out_size)
{
    (void)in_sizes; (void)n_in; (void)out_size;

    const float* xyz      = (const float*)d_in[0];
    const float* features = (const float*)d_in[1];
    const float* W1 = (const float*)d_in[2];
    const float* b1 = (const float*)d_in[3];
    const float* W2 = (const float*)d_in[4];
    const float* b2 = (const float*)d_in[5];
    const float* W3 = (const float*)d_in[6];
    const float* b3 = (const float*)d_in[7];

    float* out      = (float*)d_out;
    float* new_xyz  = out;                         // (B, P, 3)
    float* out_feat = out + (size_t)Bn * Pn * 3;   // (B, 128, P)

    const int mlp_smem = SW_FLOATS * (int)sizeof(float);      // 52736

    cudaFuncSetAttribute(fps_kernel,
                         cudaFuncAttributeMaxDynamicSharedMemorySize, FPS_SMEM);
    cudaFuncSetAttribute(group_mlp_kernel,
                         cudaFuncAttributeMaxDynamicSharedMemorySize, mlp_smem);

    fps_kernel<<<Bn * FPS_CL, FPS_NT, FPS_SMEM>>>(xyz, new_xyz);
    ballq_kernel<<<(Bn * Pn) / 8, 256>>>(xyz, new_xyz);
    group_mlp_kernel<<<(Bn * Pn) / 2, 128, mlp_smem>>>(
        xyz, features, W1, b1, W2, b2, W3, b3, new_xyz, out_feat);
}

// round 14
// speedup vs baseline: 1.1558x; 1.1558x over previous
#include <cuda_runtime.h>

// Problem constants (fixed shapes from the reference)
constexpr int Bn = 4;       // batch
constexpr int Nn = 16384;   // points per cloud
constexpr int Pn = 1024;    // npoint (FPS samples)
constexpr int Sn = 64;      // nsample (ball query)

// Scratch: ball query indices (B,P,S). 1 MB.
__device__ int g_ball_idx[Bn * Pn * Sn];

// ---- packed f32x2 helpers (sm_100+). Per-lane semantics identical to
// __fadd_rn / __fmul_rn / __fmaf_rn.
typedef unsigned long long ull;
__device__ __forceinline__ ull pk2(float lo, float hi) {
    ull r; asm("mov.b64 %0,{%1,%2};" : "=l"(r) : "f"(lo), "f"(hi)); return r;
}
__device__ __forceinline__ void upk2(ull v, float& lo, float& hi) {
    asm("mov.b64 {%0,%1},%2;" : "=f"(lo), "=f"(hi) : "l"(v));
}
__device__ __forceinline__ ull addx2(ull a, ull b) {
    ull r; asm("add.rn.f32x2 %0,%1,%2;" : "=l"(r) : "l"(a), "l"(b)); return r;
}
__device__ __forceinline__ ull mulx2(ull a, ull b) {
    ull r; asm("mul.rn.f32x2 %0,%1,%2;" : "=l"(r) : "l"(a), "l"(b)); return r;
}
__device__ __forceinline__ ull fmax2(ull a, ull b, ull c) {   // a*b+c
    ull r; asm("fma.rn.f32x2 %0,%1,%2,%3;" : "=l"(r) : "l"(a), "l"(b), "l"(c));
    return r;
}
__device__ __forceinline__ unsigned mapa_sh(unsigned addr, int rank) {
    unsigned r;
    asm("mapa.shared::cluster.u32 %0, %1, %2;" : "=r"(r) : "r"(addr), "r"(rank));
    return r;
}
__device__ __forceinline__ ull umax64(ull a, ull b) { return a > b ? a : b; }

// ---------------------------------------------------------------------------
// Kernel 1: Furthest Point Sampling — 8-CTA cluster per batch.
// (R11 version — measured best: ONE __syncthreads, lanes 0..7 parallel send.)
// Each CTA (256 threads) owns 2048 points fully in registers (packed f32x2);
// full-cloud coord copy in smem for the per-iter broadcast read.
// Per iteration:
//   redux.max (dist bits) + gated redux.min (global idx) per warp,
//   lane0 -> skey8[wid] (8 distinct slots), BAR,
//   warp0 lanes 0..7 EACH reduce the 8 keys (broadcast LDS, identical result),
//   stamp the iteration tag (bits 14..23) and store to destination CTA = lane
//   (one predicated st.shared::cluster, 8 parallel remote stores),
//   every thread polls its LOCAL mailbox (4x LDS.128) until all 8 slots carry
//   the tag, then max key => (max dist, then min global idx) == jnp.argmax.
// ---------------------------------------------------------------------------
constexpr int FPS_CL   = 8;                 // CTAs per batch (cluster size)
constexpr int FPS_PART = Nn / FPS_CL;       // 2048 points per CTA
constexpr int FPS_NT   = 256;               // threads per CTA
constexpr int FPS_PPT  = FPS_PART / FPS_NT; // 8 points per thread
constexpr int FPS_NPAIR = FPS_PPT / 2;      // 4 packed pairs per thread
// smem: float sxy[2*Nn] + szf[Nn], then ull skey8[8] + mbox[2][8]
constexpr int FPS_SMEM = 3 * Nn * 4 + 24 * 8;

__global__ __launch_bounds__(FPS_NT, 1) __cluster_dims__(FPS_CL, 1, 1)
void fps_kernel(const float* __restrict__ xyz, float* __restrict__ new_xyz)
{
    const int b = blockIdx.x / FPS_CL;
    const int r = blockIdx.x % FPS_CL;     // cluster rank
    const float* pts = xyz + (size_t)b * Nn * 3;

    extern __shared__ float sm[];
    float2* sxy   = reinterpret_cast<float2*>(sm);   // [Nn]
    float*  szf   = sm + 2 * Nn;                     // [Nn]
    ull*    skey8 = reinterpret_cast<ull*>(sm + 3 * Nn);  // [8]
    ull*    mbox  = skey8 + 8;                       // [2][8]

    const int tid  = threadIdx.x;
    const int lane = tid & 31;
    const int wid  = tid >> 5;

    // Stage the full cloud into this CTA's smem (for broadcasts).
    for (int p = tid; p < Nn; p += FPS_NT) {
        float x = pts[p * 3 + 0];
        float y = pts[p * 3 + 1];
        float z = pts[p * 3 + 2];
        sxy[p] = make_float2(x, y);
        szf[p] = z;
    }
    if (tid < 16) mbox[tid] = 0ull;        // tag 0 (never used: it >= 1)
    __syncthreads();
    // Mailbox init must be cluster-visible before any remote store (startup
    // only — no cluster barrier inside the loop).
    asm volatile("barrier.cluster.arrive.aligned;" ::: "memory");
    asm volatile("barrier.cluster.wait.aligned;"   ::: "memory");

    // Remote mailbox address: thread t<8 owns destination CTA t, slot r.
    const unsigned mbox_l  = (unsigned)__cvta_generic_to_shared(mbox);
    const unsigned rm_dest = (tid < FPS_CL)
        ? mapa_sh(mbox_l + (unsigned)(r * 8), tid) : 0u;

    // This CTA's 2048-point partition -> registers, packed pairs.
    const int base = r * FPS_PART;
    ull rx[FPS_NPAIR], ry[FPS_NPAIR], rz[FPS_NPAIR];
#pragma unroll
    for (int j = 0; j < FPS_NPAIR; ++j) {
        const int pA = base + j * FPS_NT + tid;
        const int pB = pA + FPS_NPAIR * FPS_NT;
        float2 a = sxy[pA], c = sxy[pB];
        rx[j] = pk2(a.x, c.x);
        ry[j] = pk2(a.y, c.y);
        rz[j] = pk2(szf[pA], szf[pB]);
    }
    float md[FPS_PPT];
#pragma unroll
    for (int k = 0; k < FPS_PPT; ++k) md[k] = 1e10f;   // matches jnp 1e10 init

    // First selected point is index 0.
    float qx = sxy[0].x, qy = sxy[0].y, qz = szf[0];
    if (r == 0 && tid == 0) {
        float* o = new_xyz + (size_t)b * Pn * 3;
        o[0] = qx; o[1] = qy; o[2] = qz;
    }

    for (int it = 1; it < Pn; ++it) {
        const ull nqx = pk2(-qx, -qx);
        const ull nqy = pk2(-qy, -qy);
        const ull nqz = pk2(-qz, -qz);

        float vm0 = -1.0f, vm1 = -1.0f;
#pragma unroll
        for (int j = 0; j < FPS_NPAIR; ++j) {
            ull dx = addx2(rx[j], nqx);            // == __fadd_rn(x, -qx)
            ull dy = addx2(ry[j], nqy);
            ull dz = addx2(rz[j], nqz);
            ull s  = addx2(addx2(mulx2(dx, dx), mulx2(dy, dy)), mulx2(dz, dz));
            float d0, d1; upk2(s, d0, d1);
            md[j]             = fminf(md[j],             d0);
            md[j + FPS_NPAIR] = fminf(md[j + FPS_NPAIR], d1);
            vm0 = fmaxf(vm0, md[j]);
            vm1 = fmaxf(vm1, md[j + FPS_NPAIR]);
        }
        const unsigned vb = __float_as_uint(fmaxf(vm0, vm1));

        // Warp max of distance bits (nonneg floats: bit order == float order),
        // then min global index among the warp's winners (first-match tiebreak).
        const unsigned wb = __reduce_max_sync(0xffffffffu, vb);
        unsigned loc = 0xffffffffu;
        if (vb == wb) {
            int bk = 0;
#pragma unroll
            for (int m = FPS_PPT - 1; m >= 0; --m)
                if (__float_as_uint(md[m]) == wb) bk = m;   // smallest slot
            loc = (unsigned)(base + bk * FPS_NT + tid);
        }
        const unsigned lmin = __reduce_min_sync(0xffffffffu, loc);  // <= 16383

        if (lane == 0)
            skey8[wid] = ((ull)wb << 32) | (unsigned)(0x3FFF - lmin);
        __syncthreads();

        const int buf = it & 1;
        const unsigned tag = (unsigned)(it & 0x3FF);
        if (tid < FPS_CL) {
            const ulonglong2* k2p = reinterpret_cast<const ulonglong2*>(skey8);
            ulonglong2 a0 = k2p[0], a1 = k2p[1], a2 = k2p[2], a3 = k2p[3];
            ull bk = umax64(umax64(umax64(a0.x, a0.y), umax64(a1.x, a1.y)),
                            umax64(umax64(a2.x, a2.y), umax64(a3.x, a3.y)));
            bk |= (ull)tag << 14;                  // idx bits 0..13, tag 14..23
            asm volatile("st.shared::cluster.u64 [%0], %1;"
                         :: "r"(rm_dest + (unsigned)(buf * FPS_CL * 8)),
                            "l"(bk) : "memory");
        }

        // Poll local mailbox (4x LDS.128) until all 8 slots carry this tag.
        const unsigned mba = mbox_l + (unsigned)(buf * FPS_CL * 8);
        ull k[8];
        for (;;) {
            asm volatile("ld.volatile.shared.v2.u64 {%0,%1},[%2];"
                         : "=l"(k[0]), "=l"(k[1]) : "r"(mba));
            asm volatile("ld.volatile.shared.v2.u64 {%0,%1},[%2];"
                         : "=l"(k[2]), "=l"(k[3]) : "r"(mba + 16));
            asm volatile("ld.volatile.shared.v2.u64 {%0,%1},[%2];"
                         : "=l"(k[4]), "=l"(k[5]) : "r"(mba + 32));
            asm volatile("ld.volatile.shared.v2.u64 {%0,%1},[%2];"
                         : "=l"(k[6]), "=l"(k[7]) : "r"(mba + 48));
            unsigned bad = 0;
#pragma unroll
            for (int q = 0; q < 8; ++q)
                bad |= ((unsigned)(k[q] >> 14) & 0x3FFu) ^ tag;
            if (!bad) break;
        }

        // Winner across CTAs: max packed key (max dist, then min index).
        ull kk = umax64(umax64(umax64(k[0], k[1]), umax64(k[2], k[3])),
                        umax64(umax64(k[4], k[5]), umax64(k[6], k[7])));
        const int sel = (int)(0x3FFFu - ((unsigned)kk & 0x3FFFu));

        float2 qv = sxy[sel];                      // local smem broadcast
        qx = qv.x; qy = qv.y; qz = szf[sel];
        if (r == 0 && tid == 0) {
            float* o = new_xyz + ((size_t)b * Pn + it) * 3;
            o[0] = qx; o[1] = qy; o[2] = qz;
        }
    }

    // No CTA may exit while peers might still write into its mailbox.
    asm volatile("barrier.cluster.arrive.aligned;" ::: "memory");
    asm volatile("barrier.cluster.wait.aligned;"   ::: "memory");
}

// ---------------------------------------------------------------------------
// Kernel 2: Ball query — one warp per center, 8 centers (same batch) per block.
// 128-point chunks: 12 batched loads (MLP=12 hides L2 latency), then 4
// ballots processed in index order; exit check per chunk. Output identical
// to the scalar loop (same order, same pos<Sn guards, same `first` logic).
// (R12 version — measured ~50us win.)
// ---------------------------------------------------------------------------
__global__ __launch_bounds__(256)
void ballq_kernel(const float* __restrict__ xyz, const float* __restrict__ new_xyz)
{
    const int wglobal = blockIdx.x * 8 + (threadIdx.x >> 5);  // center id 0..4095
    const int b    = wglobal >> 10;
    const int lane = threadIdx.x & 31;

    const float* pts = xyz + (size_t)b * Nn * 3;
    const float* c   = new_xyz + (size_t)wglobal * 3;
    const float cx = c[0], cy = c[1], cz = c[2];
    int* oidx = g_ball_idx + (size_t)wglobal * Sn;

    const float R2 = (float)(0.3 * 0.3);   // same double->f32 path as JAX

    int  cnt   = 0;
    int  first = 0;
    bool have  = false;

    for (int base = 0; base < Nn; base += 128) {
        float xs[4], ys[4], zs[4];
#pragma unroll
        for (int t = 0; t < 4; ++t) {
            const int j = base + t * 32 + lane;
            xs[t] = pts[j * 3 + 0];
            ys[t] = pts[j * 3 + 1];
            zs[t] = pts[j * 3 + 2];
        }
#pragma unroll
        for (int t = 0; t < 4; ++t) {
            const int j = base + t * 32 + lane;
            float dx = __fadd_rn(cx, -xs[t]);
            float dy = __fadd_rn(cy, -ys[t]);
            float dz = __fadd_rn(cz, -zs[t]);
            float d  = __fadd_rn(__fadd_rn(__fmul_rn(dx, dx), __fmul_rn(dy, dy)),
                                 __fmul_rn(dz, dz));
            bool in = d < R2;
            unsigned m = __ballot_sync(0xffffffffu, in);
            if (m) {
                if (!have) { first = base + t * 32 + (__ffs(m) - 1); have = true; }
                if (in) {
                    int pos = cnt + __popc(m & ((1u << lane) - 1u));
                    if (pos < Sn) oidx[pos] = j;
                }
                cnt += __popc(m);
            }
        }
        if (cnt >= Sn) break;
    }
    if (cnt < Sn) {
        for (int s = cnt + lane; s < Sn; s += 32) oidx[s] = first;  // 0 if none
    }
}

// ---------------------------------------------------------------------------
// Kernel 3: gather + MLP(6->64->64->128, relu) + max over samples. (unchanged)
// ---------------------------------------------------------------------------
constexpr int SW_FLOATS = 384 + 64 + 4096 + 64 + 64 * 132 + 128;  // 13184

__global__ __launch_bounds__(128)
void group_mlp_kernel(const float* __restrict__ xyz, const float* __restrict__ features,
                      const float* __restrict__ W1, const float* __restrict__ b1,
                      const float* __restrict__ W2, const float* __restrict__ b2,
                      const float* __restrict__ W3, const float* __restrict__ b3,
                      const float* __restrict__ new_xyz, float* __restrict__ out_feat)
{
    extern __shared__ float sw[];
    float* w1t = sw;                 // [6][64]   w1t[c*64+o] = W1[o][c]
    float* b1s = w1t + 384;          // [64]
    float* w2s = b1s + 64;           // [64][64]  row i = W2[i][:]
    float* b2s = w2s + 4096;         // [64]
    float* w3t = b2s + 64;           // [64][132] w3t[i*132+o] = W3[o][i]
    float* b3s = w3t + 64 * 132;     // [128]

    const int tid = threadIdx.x;

    for (int j = tid; j < 384; j += 128) {
        int cc = j >> 6, o = j & 63;
        w1t[j] = W1[o * 6 + cc];
    }
    if (tid < 64)  b1s[tid] = b1[tid];
    for (int j = tid; j < 4096; j += 128) w2s[j] = W2[j];
    if (tid < 64)  b2s[tid] = b2[tid];
    for (int j = tid; j < 8192; j += 128) {          // coalesced read, ~4-way STS
        int i = j & 63, o = j >> 6;
        w3t[i * 132 + o] = W3[j];
    }
    if (tid < 128) b3s[tid] = b3[tid];
    __syncthreads();

    const int cl = tid >> 6;                  // which of the 2 centers
    const int s  = tid & 63;                  // sample id
    const int center = blockIdx.x * 2 + cl;
    const int b  = center >> 10;
    const int gi = g_ball_idx[center * Sn + s];

    const float* pb = xyz      + (size_t)b * Nn * 3;
    const float* fb = features + (size_t)b * Nn * 3;
    const float* c  = new_xyz  + (size_t)center * 3;

    float g[6];
    g[0] = pb[gi * 3 + 0] - c[0];
    g[1] = pb[gi * 3 + 1] - c[1];
    g[2] = pb[gi * 3 + 2] - c[2];
    g[3] = fb[gi * 3 + 0];
    g[4] = fb[gi * 3 + 1];
    g[5] = fb[gi * 3 + 2];

    // ---- layer 1 (packed: 64 outputs in 32 ull regs) ----
    ull h1p[32];
    {
        const ull* b1u = reinterpret_cast<const ull*>(b1s);
#pragma unroll
        for (int k = 0; k < 32; ++k) h1p[k] = b1u[k];
    }
#pragma unroll
    for (int cc = 0; cc < 6; ++cc) {
        const ull gv = pk2(g[cc], g[cc]);
        const ull* wr = reinterpret_cast<const ull*>(w1t + cc * 64);
#pragma unroll
        for (int k = 0; k < 32; ++k) h1p[k] = fmax2(wr[k], gv, h1p[k]);
    }
#pragma unroll
    for (int k = 0; k < 32; ++k) {        // relu
        float lo, hi; upk2(h1p[k], lo, hi);
        h1p[k] = pk2(fmaxf(lo, 0.0f), fmaxf(hi, 0.0f));
    }

    // ---- layer 2: materialize h2[64] (h1p dies after this loop) ----
    float h2[64];
#pragma unroll
    for (int i = 0; i < 64; ++i) {
        const ulonglong2* w2r =
            reinterpret_cast<const ulonglong2*>(w2s + (i << 6));
        ull a0 = 0ull, a1 = 0ull, a2 = 0ull, a3 = 0ull;   // (0,0) packed
#pragma unroll
        for (int q = 0; q < 16; q += 2) {
            ulonglong2 w = w2r[q];
            ulonglong2 v = w2r[q + 1];
            a0 = fmax2(w.x, h1p[2 * q + 0], a0);
            a1 = fmax2(w.y, h1p[2 * q + 1], a1);
            a2 = fmax2(v.x, h1p[2 * q + 2], a2);
            a3 = fmax2(v.y, h1p[2 * q + 3], a3);
        }
        ull sp = addx2(addx2(a0, a1), addx2(a2, a3));
        float lo, hi; upk2(sp, lo, hi);
        h2[i] = fmaxf((lo + hi) + b2s[i], 0.0f);
    }

    // ---- layer 3 in two chunks of 64 outputs + warp-level max (REDUX) ----
    __shared__ unsigned red[4][128];
    const int wid = tid >> 5, lane = tid & 31;

    for (int ch = 0; ch < 2; ++ch) {
        ull accp[32];
        {
            const ull* b3u = reinterpret_cast<const ull*>(b3s + ch * 64);
#pragma unroll
            for (int k = 0; k < 32; ++k) accp[k] = b3u[k];
        }
#pragma unroll
        for (int i = 0; i < 64; ++i) {
            const ull h2p = pk2(h2[i], h2[i]);
            const ulonglong2* w3r =
                reinterpret_cast<const ulonglong2*>(w3t + i * 132 + ch * 64);
#pragma unroll
            for (int q = 0; q < 16; ++q) {
                ulonglong2 w = w3r[q];
                accp[2 * q + 0] = fmax2(w.x, h2p, accp[2 * q + 0]);
                accp[2 * q + 1] = fmax2(w.y, h2p, accp[2 * q + 1]);
            }
        }
        // relu + per-warp max over 32 samples (one REDUX per output)
#pragma unroll
        for (int k = 0; k < 32; ++k) {
            float lo, hi; upk2(accp[k], lo, hi);
            unsigned mlo = __reduce_max_sync(
                0xffffffffu, __float_as_uint(fmaxf(lo, 0.0f)));
            unsigned mhi = __reduce_max_sync(
                0xffffffffu, __float_as_uint(fmaxf(hi, 0.0f)));
            if (lane == 0) {
                red[wid][ch * 64 + 2 * k + 0] = mlo;
                red[wid][ch * 64 + 2 * k + 1] = mhi;
            }
        }
    }
    __syncthreads();

    // Combine the two warps of each center; write (B,128,P) layout.
    for (int t = tid; t < 256; t += 128) {
        int cc = t >> 7, oo = t & 127;
        unsigned v = red[2 * cc][oo] > red[2 * cc + 1][oo]
                   ? red[2 * cc][oo] : red[2 * cc + 1][oo];
        int ctr = blockIdx.x * 2 + cc;
        int bb = ctr >> 10, pp = ctr & 1023;
        out_feat[(size_t)bb * (128 * Pn) + (size_t)oo * Pn + pp] =
            __uint_as_float(v);
    }
}

// ---------------------------------------------------------------------------
// Launch: fps (clustered) -> ball query -> group+MLP.
// Output = [new_xyz | new_features].
// ---------------------------------------------------------------------------
extern "C" void kernel_launch(void* const* d_in, const int* in_sizes, int n_in,
                              void* d_out, int out_size)
{
    (void)in_sizes; (void)n_in; (void)out_size;

    const float* xyz      = (const float*)d_in[0];
    const float* features = (const float*)d_in[1];
    const float* W1 = (const float*)d_in[2];
    const float* b1 = (const float*)d_in[3];
    const float* W2 = (const float*)d_in[4];
    const float* b2 = (const float*)d_in[5];
    const float* W3 = (const float*)d_in[6];
    const float* b3 = (const float*)d_in[7];

    float* out      = (float*)d_out;
    float* new_xyz  = out;                         // (B, P, 3)
    float* out_feat = out + (size_t)Bn * Pn * 3;   // (B, 128, P)

    const int mlp_smem = SW_FLOATS * (int)sizeof(float);      // 52736

    cudaFuncSetAttribute(fps_kernel,
                         cudaFuncAttributeMaxDynamicSharedMemorySize, FPS_SMEM);
    cudaFuncSetAttribute(group_mlp_kernel,
                         cudaFuncAttributeMaxDynamicSharedMemorySize, mlp_smem);

    fps_kernel<<<Bn * FPS_CL, FPS_NT, FPS_SMEM>>>(xyz, new_xyz);
    ballq_kernel<<<(Bn * Pn) / 8, 256>>>(xyz, new_xyz);
    group_mlp_kernel<<<(Bn * Pn) / 2, 128, mlp_smem>>>(
        xyz, features, W1, b1, W2, b2, W3, b3, new_xyz, out_feat);
}

// round 16
// speedup vs baseline: 1.2154x; 1.0515x over previous
#include <cuda_runtime.h>

// Problem constants (fixed shapes from the reference)
constexpr int Bn = 4;       // batch
constexpr int Nn = 16384;   // points per cloud
constexpr int Pn = 1024;    // npoint (FPS samples)
constexpr int Sn = 64;      // nsample (ball query)

// Scratch: ball query indices (B,P,S). 1 MB.
__device__ int g_ball_idx[Bn * Pn * Sn];
// Cross-kernel progress flags (reset every call by reset_kernel).
__device__ int g_progress[Bn];          // FPS iterations published per batch
__device__ int g_bflag[(Bn * Pn) / 8];  // ballq block-done flags (512)

// ---- packed f32x2 helpers (sm_100+). Per-lane semantics identical to
// __fadd_rn / __fmul_rn / __fmaf_rn.
typedef unsigned long long ull;
__device__ __forceinline__ ull pk2(float lo, float hi) {
    ull r; asm("mov.b64 %0,{%1,%2};" : "=l"(r) : "f"(lo), "f"(hi)); return r;
}
__device__ __forceinline__ void upk2(ull v, float& lo, float& hi) {
    asm("mov.b64 {%0,%1},%2;" : "=f"(lo), "=f"(hi) : "l"(v));
}
__device__ __forceinline__ ull addx2(ull a, ull b) {
    ull r; asm("add.rn.f32x2 %0,%1,%2;" : "=l"(r) : "l"(a), "l"(b)); return r;
}
__device__ __forceinline__ ull mulx2(ull a, ull b) {
    ull r; asm("mul.rn.f32x2 %0,%1,%2;" : "=l"(r) : "l"(a), "l"(b)); return r;
}
__device__ __forceinline__ ull fmax2(ull a, ull b, ull c) {   // a*b+c
    ull r; asm("fma.rn.f32x2 %0,%1,%2,%3;" : "=l"(r) : "l"(a), "l"(b), "l"(c));
    return r;
}
__device__ __forceinline__ unsigned mapa_sh(unsigned addr, int rank) {
    unsigned r;
    asm("mapa.shared::cluster.u32 %0, %1, %2;" : "=r"(r) : "r"(addr), "r"(rank));
    return r;
}
__device__ __forceinline__ ull umax64(ull a, ull b) { return a > b ? a : b; }

__device__ __forceinline__ int ld_acq(const int* p) {
    int v;
    asm volatile("ld.acquire.gpu.global.b32 %0, [%1];"
                 : "=r"(v) : "l"(p) : "memory");
    return v;
}
__device__ __forceinline__ void st_rel(int* p, int v) {
    asm volatile("st.global.release.gpu.b32 [%0], %1;"
                 :: "l"(p), "r"(v) : "memory");
}
__device__ __forceinline__ void launch_dependents() {
    asm volatile("griddepcontrol.launch_dependents;");
}
// L2-coherent loads (bypass L1 / non-coherent caches) for data written by a
// concurrently running producer kernel.
__device__ __forceinline__ float ldcg_f(const float* p) {
    float v;
    asm volatile("ld.global.cg.f32 %0, [%1];" : "=f"(v) : "l"(p) : "memory");
    return v;
}
__device__ __forceinline__ int ldcg_i(const int* p) {
    int v;
    asm volatile("ld.global.cg.b32 %0, [%1];" : "=r"(v) : "l"(p) : "memory");
    return v;
}

// ---------------------------------------------------------------------------
// Kernel 0: reset cross-kernel flags (runs first, every call/replay).
// ---------------------------------------------------------------------------
__global__ void reset_kernel()
{
    const int t = threadIdx.x;
    if (t < Bn) g_progress[t] = 0;
    for (int i = t; i < (Bn * Pn) / 8; i += 256) g_bflag[i] = 0;
}

// ---------------------------------------------------------------------------
// Kernel 1: Furthest Point Sampling — 8-CTA cluster per batch (R13 compute)
// + PDL trigger at startup + per-batch progress publish every 8 iterations.
// The 192KB smem doubles as an occupancy shield: MLP blocks can't co-reside
// on FPS's SMs, so the overlapped MLP fills only the 116 idle SMs.
// ---------------------------------------------------------------------------
constexpr int FPS_CL   = 8;                 // CTAs per batch (cluster size)
constexpr int FPS_PART = Nn / FPS_CL;       // 2048 points per CTA
constexpr int FPS_NT   = 256;               // threads per CTA
constexpr int FPS_PPT  = FPS_PART / FPS_NT; // 8 points per thread
constexpr int FPS_NPAIR = FPS_PPT / 2;      // 4 packed pairs per thread
// smem: float sxy[2*Nn] + szf[Nn], then ull skey8[8] + mbox[2][8]
constexpr int FPS_SMEM = 3 * Nn * 4 + 24 * 8;

__global__ __launch_bounds__(FPS_NT, 1) __cluster_dims__(FPS_CL, 1, 1)
void fps_kernel(const float* __restrict__ xyz, float* __restrict__ new_xyz)
{
    const int b = blockIdx.x / FPS_CL;
    const int r = blockIdx.x % FPS_CL;     // cluster rank
    const float* pts = xyz + (size_t)b * Nn * 3;

    extern __shared__ float sm[];
    float2* sxy   = reinterpret_cast<float2*>(sm);   // [Nn]
    float*  szf   = sm + 2 * Nn;                     // [Nn]
    ull*    skey8 = reinterpret_cast<ull*>(sm + 3 * Nn);  // [8]
    ull*    mbox  = skey8 + 8;                       // [2][8]

    const int tid  = threadIdx.x;
    const int lane = tid & 31;
    const int wid  = tid >> 5;

    // Stage the full cloud into this CTA's smem (for broadcasts).
    for (int p = tid; p < Nn; p += FPS_NT) {
        float x = pts[p * 3 + 0];
        float y = pts[p * 3 + 1];
        float z = pts[p * 3 + 2];
        sxy[p] = make_float2(x, y);
        szf[p] = z;
    }
    if (tid < 16) mbox[tid] = 0ull;        // tag 0 (never used: it >= 1)
    __syncthreads();
    // Mailbox init must be cluster-visible before any remote store (startup
    // only — no cluster barrier inside the loop).
    asm volatile("barrier.cluster.arrive.aligned;" ::: "memory");
    asm volatile("barrier.cluster.wait.aligned;"   ::: "memory");

    // Allow ballq/MLP grids to launch and start placing now.
    launch_dependents();

    // Remote mailbox address: thread t<8 owns destination CTA t, slot r.
    const unsigned mbox_l  = (unsigned)__cvta_generic_to_shared(mbox);
    const unsigned rm_dest = (tid < FPS_CL)
        ? mapa_sh(mbox_l + (unsigned)(r * 8), tid) : 0u;

    // This CTA's 2048-point partition -> registers, packed pairs.
    const int base = r * FPS_PART;
    ull rx[FPS_NPAIR], ry[FPS_NPAIR], rz[FPS_NPAIR];
#pragma unroll
    for (int j = 0; j < FPS_NPAIR; ++j) {
        const int pA = base + j * FPS_NT + tid;
        const int pB = pA + FPS_NPAIR * FPS_NT;
        float2 a = sxy[pA], c = sxy[pB];
        rx[j] = pk2(a.x, c.x);
        ry[j] = pk2(a.y, c.y);
        rz[j] = pk2(szf[pA], szf[pB]);
    }
    float md[FPS_PPT];
#pragma unroll
    for (int k = 0; k < FPS_PPT; ++k) md[k] = 1e10f;   // matches jnp 1e10 init

    // First selected point is index 0.
    float qx = sxy[0].x, qy = sxy[0].y, qz = szf[0];
    if (r == 0 && tid == 0) {
        float* o = new_xyz + (size_t)b * Pn * 3;
        o[0] = qx; o[1] = qy; o[2] = qz;
    }

    for (int it = 1; it < Pn; ++it) {
        const ull nqx = pk2(-qx, -qx);
        const ull nqy = pk2(-qy, -qy);
        const ull nqz = pk2(-qz, -qz);

        float vm0 = -1.0f, vm1 = -1.0f;
#pragma unroll
        for (int j = 0; j < FPS_NPAIR; ++j) {
            ull dx = addx2(rx[j], nqx);            // == __fadd_rn(x, -qx)
            ull dy = addx2(ry[j], nqy);
            ull dz = addx2(rz[j], nqz);
            ull s  = addx2(addx2(mulx2(dx, dx), mulx2(dy, dy)), mulx2(dz, dz));
            float d0, d1; upk2(s, d0, d1);
            md[j]             = fminf(md[j],             d0);
            md[j + FPS_NPAIR] = fminf(md[j + FPS_NPAIR], d1);
            vm0 = fmaxf(vm0, md[j]);
            vm1 = fmaxf(vm1, md[j + FPS_NPAIR]);
        }
        const unsigned vb = __float_as_uint(fmaxf(vm0, vm1));

        // Warp max of distance bits (nonneg floats: bit order == float order),
        // then min global index among the warp's winners (first-match tiebreak).
        const unsigned wb = __reduce_max_sync(0xffffffffu, vb);
        unsigned loc = 0xffffffffu;
        if (vb == wb) {
            int bk = 0;
#pragma unroll
            for (int m = FPS_PPT - 1; m >= 0; --m)
                if (__float_as_uint(md[m]) == wb) bk = m;   // smallest slot
            loc = (unsigned)(base + bk * FPS_NT + tid);
        }
        const unsigned lmin = __reduce_min_sync(0xffffffffu, loc);  // <= 16383

        if (lane == 0)
            skey8[wid] = ((ull)wb << 32) | (unsigned)(0x3FFF - lmin);
        __syncthreads();

        const int buf = it & 1;
        const unsigned tag = (unsigned)(it & 0x3FF);
        if (tid < FPS_CL) {
            const ulonglong2* k2p = reinterpret_cast<const ulonglong2*>(skey8);
            ulonglong2 a0 = k2p[0], a1 = k2p[1], a2 = k2p[2], a3 = k2p[3];
            ull bk = umax64(umax64(umax64(a0.x, a0.y), umax64(a1.x, a1.y)),
                            umax64(umax64(a2.x, a2.y), umax64(a3.x, a3.y)));
            bk |= (ull)tag << 14;                  // idx bits 0..13, tag 14..23
            asm volatile("st.shared::cluster.u64 [%0], %1;"
                         :: "r"(rm_dest + (unsigned)(buf * FPS_CL * 8)),
                            "l"(bk) : "memory");
        }

        // Poll local mailbox (4x LDS.128) until all 8 slots carry this tag.
        const unsigned mba = mbox_l + (unsigned)(buf * FPS_CL * 8);
        ull k[8];
        for (;;) {
            asm volatile("ld.volatile.shared.v2.u64 {%0,%1},[%2];"
                         : "=l"(k[0]), "=l"(k[1]) : "r"(mba));
            asm volatile("ld.volatile.shared.v2.u64 {%0,%1},[%2];"
                         : "=l"(k[2]), "=l"(k[3]) : "r"(mba + 16));
            asm volatile("ld.volatile.shared.v2.u64 {%0,%1},[%2];"
                         : "=l"(k[4]), "=l"(k[5]) : "r"(mba + 32));
            asm volatile("ld.volatile.shared.v2.u64 {%0,%1},[%2];"
                         : "=l"(k[6]), "=l"(k[7]) : "r"(mba + 48));
            unsigned bad = 0;
#pragma unroll
            for (int q = 0; q < 8; ++q)
                bad |= ((unsigned)(k[q] >> 14) & 0x3FFu) ^ tag;
            if (!bad) break;
        }

        // Winner across CTAs: max packed key (max dist, then min index).
        ull kk = umax64(umax64(umax64(k[0], k[1]), umax64(k[2], k[3])),
                        umax64(umax64(k[4], k[5]), umax64(k[6], k[7])));
        const int sel = (int)(0x3FFFu - ((unsigned)kk & 0x3FFFu));

        float2 qv = sxy[sel];                      // local smem broadcast
        qx = qv.x; qy = qv.y; qz = szf[sel];
        if (r == 0 && tid == 0) {
            float* o = new_xyz + ((size_t)b * Pn + it) * 3;
            o[0] = qx; o[1] = qy; o[2] = qz;
            if ((it & 7) == 7)                      // publish progress (release
                st_rel(g_progress + b, it + 1);     // orders the coord stores)
        }
    }

    // No CTA may exit while peers might still write into its mailbox.
    asm volatile("barrier.cluster.arrive.aligned;" ::: "memory");
    asm volatile("barrier.cluster.wait.aligned;"   ::: "memory");
}

// ---------------------------------------------------------------------------
// Kernel 2: Ball query — one warp per center, 8 centers (same batch) per block.
// PDL secondary: spins on FPS progress for its 8 centers. Center coords read
// with ld.global.cg (L2-coherent; L1/nc would hold stale lines fetched by
// earlier blocks on the same SM while FPS was still writing those centers).
// ---------------------------------------------------------------------------
__global__ __launch_bounds__(256)
void ballq_kernel(const float* __restrict__ xyz, const float* new_xyz)
{
    launch_dependents();                    // let the MLP grid launch too

    const int bid = blockIdx.x;
    if (threadIdx.x == 0) {
        const int bb   = bid >> 7;                       // batch
        const int need = ((bid & 127) << 3) + 8;         // local centers +8
        while (ld_acq(g_progress + bb) < need) __nanosleep(128);
    }
    __syncthreads();

    const int wglobal = bid * 8 + (threadIdx.x >> 5);  // center id 0..4095
    const int b    = wglobal >> 10;
    const int lane = threadIdx.x & 31;

    const float* pts = xyz + (size_t)b * Nn * 3;
    const float* c   = new_xyz + (size_t)wglobal * 3;
    const float cx = ldcg_f(c + 0);
    const float cy = ldcg_f(c + 1);
    const float cz = ldcg_f(c + 2);
    int* oidx = g_ball_idx + (size_t)wglobal * Sn;

    const float R2 = (float)(0.3 * 0.3);   // same double->f32 path as JAX

    int  cnt   = 0;
    int  first = 0;
    bool have  = false;

    for (int base = 0; base < Nn; base += 128) {
        float xs[4], ys[4], zs[4];
#pragma unroll
        for (int t = 0; t < 4; ++t) {
            const int j = base + t * 32 + lane;
            xs[t] = pts[j * 3 + 0];
            ys[t] = pts[j * 3 + 1];
            zs[t] = pts[j * 3 + 2];
        }
#pragma unroll
        for (int t = 0; t < 4; ++t) {
            const int j = base + t * 32 + lane;
            float dx = __fadd_rn(cx, -xs[t]);
            float dy = __fadd_rn(cy, -ys[t]);
            float dz = __fadd_rn(cz, -zs[t]);
            float d  = __fadd_rn(__fadd_rn(__fmul_rn(dx, dx), __fmul_rn(dy, dy)),
                                 __fmul_rn(dz, dz));
            bool in = d < R2;
            unsigned m = __ballot_sync(0xffffffffu, in);
            if (m) {
                if (!have) { first = base + t * 32 + (__ffs(m) - 1); have = true; }
                if (in) {
                    int pos = cnt + __popc(m & ((1u << lane) - 1u));
                    if (pos < Sn) oidx[pos] = j;
                }
                cnt += __popc(m);
            }
        }
        if (cnt >= Sn) break;
    }
    if (cnt < Sn) {
        for (int s = cnt + lane; s < Sn; s += 32) oidx[s] = first;  // 0 if none
    }

    __syncthreads();
    if (threadIdx.x == 0) {
        __threadfence();                    // drain all warps' idx stores
        st_rel(g_bflag + bid, 1);
    }
}

// ---------------------------------------------------------------------------
// Kernel 3: gather + MLP(6->64->64->128, relu) + max over samples.
// PDL secondary: stages weights (overlap), spins on the ballq done flag, then
// reads idx + center coords with ld.global.cg (L2-coherent). Compute = R13.
// ---------------------------------------------------------------------------
constexpr int SW_FLOATS = 384 + 64 + 4096 + 64 + 64 * 132 + 128;  // 13184

__global__ __launch_bounds__(128)
void group_mlp_kernel(const float* __restrict__ xyz, const float* __restrict__ features,
                      const float* __restrict__ W1, const float* __restrict__ b1,
                      const float* __restrict__ W2, const float* __restrict__ b2,
                      const float* __restrict__ W3, const float* __restrict__ b3,
                      const float* new_xyz, float* __restrict__ out_feat)
{
    extern __shared__ float sw[];
    float* w1t = sw;                 // [6][64]   w1t[c*64+o] = W1[o][c]
    float* b1s = w1t + 384;          // [64]
    float* w2s = b1s + 64;           // [64][64]  row i = W2[i][:]
    float* b2s = w2s + 4096;         // [64]
    float* w3t = b2s + 64;           // [64][132] w3t[i*132+o] = W3[o][i]
    float* b3s = w3t + 64 * 132;     // [128]

    const int tid = threadIdx.x;

    for (int j = tid; j < 384; j += 128) {
        int cc = j >> 6, o = j & 63;
        w1t[j] = W1[o * 6 + cc];
    }
    if (tid < 64)  b1s[tid] = b1[tid];
    for (int j = tid; j < 4096; j += 128) w2s[j] = W2[j];
    if (tid < 64)  b2s[tid] = b2[tid];
    for (int j = tid; j < 8192; j += 128) {          // coalesced read, ~4-way STS
        int i = j & 63, o = j >> 6;
        w3t[i * 132 + o] = W3[j];
    }
    if (tid < 128) b3s[tid] = b3[tid];

    // Wait for the ballq block covering our 2 centers (weights staged above
    // overlap with the spin).
    if (tid == 0) {
        while (ld_acq(g_bflag + (blockIdx.x >> 2)) == 0) __nanosleep(128);
    }
    __syncthreads();

    const int cl = tid >> 6;                  // which of the 2 centers
    const int s  = tid & 63;                  // sample id
    const int center = blockIdx.x * 2 + cl;
    const int b  = center >> 10;
    const int gi = ldcg_i(g_ball_idx + center * Sn + s);

    const float* pb = xyz      + (size_t)b * Nn * 3;
    const float* fb = features + (size_t)b * Nn * 3;
    const float* c  = new_xyz  + (size_t)center * 3;

    float g[6];
    g[0] = pb[gi * 3 + 0] - ldcg_f(c + 0);
    g[1] = pb[gi * 3 + 1] - ldcg_f(c + 1);
    g[2] = pb[gi * 3 + 2] - ldcg_f(c + 2);
    g[3] = fb[gi * 3 + 0];
    g[4] = fb[gi * 3 + 1];
    g[5] = fb[gi * 3 + 2];

    // ---- layer 1 (packed: 64 outputs in 32 ull regs) ----
    ull h1p[32];
    {
        const ull* b1u = reinterpret_cast<const ull*>(b1s);
#pragma unroll
        for (int k = 0; k < 32; ++k) h1p[k] = b1u[k];
    }
#pragma unroll
    for (int cc = 0; cc < 6; ++cc) {
        const ull gv = pk2(g[cc], g[cc]);
        const ull* wr = reinterpret_cast<const ull*>(w1t + cc * 64);
#pragma unroll
        for (int k = 0; k < 32; ++k) h1p[k] = fmax2(wr[k], gv, h1p[k]);
    }
#pragma unroll
    for (int k = 0; k < 32; ++k) {        // relu
        float lo, hi; upk2(h1p[k], lo, hi);
        h1p[k] = pk2(fmaxf(lo, 0.0f), fmaxf(hi, 0.0f));
    }

    // ---- layer 2: materialize h2[64] (h1p dies after this loop) ----
    float h2[64];
#pragma unroll
    for (int i = 0; i < 64; ++i) {
        const ulonglong2* w2r =
            reinterpret_cast<const ulonglong2*>(w2s + (i << 6));
        ull a0 = 0ull, a1 = 0ull, a2 = 0ull, a3 = 0ull;   // (0,0) packed
#pragma unroll
        for (int q = 0; q < 16; q += 2) {
            ulonglong2 w = w2r[q];
            ulonglong2 v = w2r[q + 1];
            a0 = fmax2(w.x, h1p[2 * q + 0], a0);
            a1 = fmax2(w.y, h1p[2 * q + 1], a1);
            a2 = fmax2(v.x, h1p[2 * q + 2], a2);
            a3 = fmax2(v.y, h1p[2 * q + 3], a3);
        }
        ull sp = addx2(addx2(a0, a1), addx2(a2, a3));
        float lo, hi; upk2(sp, lo, hi);
        h2[i] = fmaxf((lo + hi) + b2s[i], 0.0f);
    }

    // ---- layer 3 in two chunks of 64 outputs + warp-level max (REDUX) ----
    __shared__ unsigned red[4][128];
    const int wid = tid >> 5, lane = tid & 31;

    for (int ch = 0; ch < 2; ++ch) {
        ull accp[32];
        {
            const ull* b3u = reinterpret_cast<const ull*>(b3s + ch * 64);
#pragma unroll
            for (int k = 0; k < 32; ++k) accp[k] = b3u[k];
        }
#pragma unroll
        for (int i = 0; i < 64; ++i) {
            const ull h2p = pk2(h2[i], h2[i]);
            const ulonglong2* w3r =
                reinterpret_cast<const ulonglong2*>(w3t + i * 132 + ch * 64);
#pragma unroll
            for (int q = 0; q < 16; ++q) {
                ulonglong2 w = w3r[q];
                accp[2 * q + 0] = fmax2(w.x, h2p, accp[2 * q + 0]);
                accp[2 * q + 1] = fmax2(w.y, h2p, accp[2 * q + 1]);
            }
        }
        // relu + per-warp max over 32 samples (one REDUX per output)
#pragma unroll
        for (int k = 0; k < 32; ++k) {
            float lo, hi; upk2(accp[k], lo, hi);
            unsigned mlo = __reduce_max_sync(
                0xffffffffu, __float_as_uint(fmaxf(lo, 0.0f)));
            unsigned mhi = __reduce_max_sync(
                0xffffffffu, __float_as_uint(fmaxf(hi, 0.0f)));
            if (lane == 0) {
                red[wid][ch * 64 + 2 * k + 0] = mlo;
                red[wid][ch * 64 + 2 * k + 1] = mhi;
            }
        }
    }
    __syncthreads();

    // Combine the two warps of each center; write (B,128,P) layout.
    for (int t = tid; t < 256; t += 128) {
        int cc = t >> 7, oo = t & 127;
        unsigned v = red[2 * cc][oo] > red[2 * cc + 1][oo]
                   ? red[2 * cc][oo] : red[2 * cc + 1][oo];
        int ctr = blockIdx.x * 2 + cc;
        int bb = ctr >> 10, pp = ctr & 1023;
        out_feat[(size_t)bb * (128 * Pn) + (size_t)oo * Pn + pp] =
            __uint_as_float(v);
    }
}

// ---------------------------------------------------------------------------
// Launch: reset -> fps, with ballq and mlp PDL-overlapped behind fps.
// Output = [new_xyz | new_features].
// ---------------------------------------------------------------------------
extern "C" void kernel_launch(void* const* d_in, const int* in_sizes, int n_in,
                              void* d_out, int out_size)
{
    (void)in_sizes; (void)n_in; (void)out_size;

    const float* xyz      = (const float*)d_in[0];
    const float* features = (const float*)d_in[1];
    const float* W1 = (const float*)d_in[2];
    const float* b1 = (const float*)d_in[3];
    const float* W2 = (const float*)d_in[4];
    const float* b2 = (const float*)d_in[5];
    const float* W3 = (const float*)d_in[6];
    const float* b3 = (const float*)d_in[7];

    float* out      = (float*)d_out;
    float* new_xyz  = out;                         // (B, P, 3)
    float* out_feat = out + (size_t)Bn * Pn * 3;   // (B, 128, P)

    const int mlp_smem = SW_FLOATS * (int)sizeof(float);      // 52736

    cudaFuncSetAttribute(fps_kernel,
                         cudaFuncAttributeMaxDynamicSharedMemorySize, FPS_SMEM);
    cudaFuncSetAttribute(group_mlp_kernel,
                         cudaFuncAttributeMaxDynamicSharedMemorySize, mlp_smem);

    reset_kernel<<<1, 256>>>();
    fps_kernel<<<Bn * FPS_CL, FPS_NT, FPS_SMEM>>>(xyz, new_xyz);

    // PDL attribute: allow these grids to launch once fps triggers.
    cudaLaunchAttribute pdl[1];
    pdl[0].id = cudaLaunchAttributeProgrammaticStreamSerialization;
    pdl[0].val.programmaticStreamSerializationAllowed = 1;

    cudaLaunchConfig_t cfgB = {};
    cfgB.gridDim  = dim3((Bn * Pn) / 8);
    cfgB.blockDim = dim3(256);
    cfgB.dynamicSmemBytes = 0;
    cfgB.stream = 0;
    cfgB.attrs = pdl;
    cfgB.numAttrs = 1;
    if (cudaLaunchKernelEx(&cfgB, ballq_kernel, xyz,
                           (const float*)new_xyz) != cudaSuccess) {
        ballq_kernel<<<(Bn * Pn) / 8, 256>>>(xyz, new_xyz);
    }

    cudaLaunchConfig_t cfgM = {};
    cfgM.gridDim  = dim3((Bn * Pn) / 2);
    cfgM.blockDim = dim3(128);
    cfgM.dynamicSmemBytes = mlp_smem;
    cfgM.stream = 0;
    cfgM.attrs = pdl;
    cfgM.numAttrs = 1;
    if (cudaLaunchKernelEx(&cfgM, group_mlp_kernel, xyz, features,
                           W1, b1, W2, b2, W3, b3,
                           (const float*)new_xyz, out_feat) != cudaSuccess) {
        group_mlp_kernel<<<(Bn * Pn) / 2, 128, mlp_smem>>>(
            xyz, features, W1, b1, W2, b2, W3, b3, new_xyz, out_feat);
    }
}